// round 2
// baseline (speedup 1.0000x reference)
#include <cuda_runtime.h>
#include <cuda_bf16.h>
#include <math.h>

// Problem constants (fixed by the reference)
#define BS 2
#define NQ 21760          // queries = total spatial positions
#define NV 21760          // value rows
#define CDIM 256
#define NHEADS 8
#define DHEAD 32
#define NLEV 4
#define NPTS 4
#define MROWS (BS * NQ)   // 43520

// Level geometry (compile-time)
__device__ __constant__ int LVL_W[4] = {128, 64, 32, 16};
__device__ __constant__ int LVL_H[4] = {128, 64, 32, 16};
__device__ __constant__ int LVL_S[4] = {0, 16384, 20480, 21504};

// Scratch (allocation-free rule: __device__ globals)
__device__ float g_val [MROWS * 256];   // value @ W_v + b_v          [bs*V, 256]
__device__ float g_off [MROWS * 256];   // query @ W_off + b_off      [bs*Q, 256]
__device__ float g_attn[MROWS * 128];   // query @ W_attn + b_attn    [bs*Q, 128]
__device__ float g_samp[MROWS * 256];   // deformable-attn output     [bs*Q, 256]

// ---------------------------------------------------------------------------
// fp32 SIMT GEMM: C[M,N] = A[M,256] @ B[256,N] + bias[N]
// Tile 128x128x16, 256 threads, 8x8 micro-tile per thread.
// Requires M % 128 == 0 and N % 128 == 0 (M=43520=340*128, N in {128,256}).
// ---------------------------------------------------------------------------
#define BM 128
#define BN 128
#define BK 16
#define TM 8
#define TN 8
#define APAD 132   // 132*4 = 528 bytes per k-plane: 16B-aligned, reduces store conflicts

__global__ __launch_bounds__(256)
void gemm_k256(const float* __restrict__ A, const float* __restrict__ B,
               const float* __restrict__ bias, float* __restrict__ C, int N) {
    __shared__ float As[BK][APAD];
    __shared__ float Bs[BK][BN];

    const int bm = blockIdx.x * BM;
    const int bn = blockIdx.y * BN;
    const int tid = threadIdx.x;
    const int tx = tid & 15;   // N direction (16 * 8 = 128)
    const int ty = tid >> 4;   // M direction (16 * 8 = 128)

    const int aRow = tid >> 2;        // 0..63 (two passes -> 128 rows)
    const int aCol = (tid & 3) * 4;   // 0,4,8,12
    const int bRow = tid >> 5;        // 0..7  (two passes -> 16 rows)
    const int bCol = (tid & 31) * 4;  // 0..124

    float acc[TM][TN];
#pragma unroll
    for (int i = 0; i < TM; i++)
#pragma unroll
        for (int j = 0; j < TN; j++) acc[i][j] = 0.0f;

    const int K = 256;
    for (int k0 = 0; k0 < K; k0 += BK) {
#pragma unroll
        for (int r = 0; r < 2; r++) {
            int row = aRow + r * 64;
            float4 v = *(const float4*)&A[(size_t)(bm + row) * K + k0 + aCol];
            As[aCol + 0][row] = v.x;
            As[aCol + 1][row] = v.y;
            As[aCol + 2][row] = v.z;
            As[aCol + 3][row] = v.w;
        }
#pragma unroll
        for (int r = 0; r < 2; r++) {
            int row = bRow + r * 8;
            float4 v = *(const float4*)&B[(size_t)(k0 + row) * N + bn + bCol];
            *(float4*)&Bs[row][bCol] = v;
        }
        __syncthreads();

#pragma unroll
        for (int kk = 0; kk < BK; kk++) {
            float4 a0 = *(const float4*)&As[kk][ty * TM];
            float4 a1 = *(const float4*)&As[kk][ty * TM + 4];
            float4 b0 = *(const float4*)&Bs[kk][tx * TN];
            float4 b1 = *(const float4*)&Bs[kk][tx * TN + 4];
            float ra[TM] = {a0.x, a0.y, a0.z, a0.w, a1.x, a1.y, a1.z, a1.w};
            float rb[TN] = {b0.x, b0.y, b0.z, b0.w, b1.x, b1.y, b1.z, b1.w};
#pragma unroll
            for (int i = 0; i < TM; i++)
#pragma unroll
                for (int j = 0; j < TN; j++)
                    acc[i][j] = fmaf(ra[i], rb[j], acc[i][j]);
        }
        __syncthreads();
    }

#pragma unroll
    for (int i = 0; i < TM; i++) {
        int row = bm + ty * TM + i;
#pragma unroll
        for (int j = 0; j < TN; j += 4) {
            int col = bn + tx * TN + j;
            float4 v;
            v.x = acc[i][j + 0] + bias[col + 0];
            v.y = acc[i][j + 1] + bias[col + 1];
            v.z = acc[i][j + 2] + bias[col + 2];
            v.w = acc[i][j + 3] + bias[col + 3];
            *(float4*)&C[(size_t)row * N + col] = v;
        }
    }
}

// ---------------------------------------------------------------------------
// Deformable sampler: one warp per (b, q, h). Lane = channel within head.
//   - softmax over the 16 attn logits via warp shuffles (lanes 0..15)
//   - offsets for point p sit at lanes 2p, 2p+1 of the 32-float head slice
//   - each corner gather = one coalesced 128B line (32 contiguous floats)
// ---------------------------------------------------------------------------
__global__ __launch_bounds__(256)
void sampler(const float* __restrict__ val, const float* __restrict__ off,
             const float* __restrict__ logits, const float* __restrict__ refp,
             float* __restrict__ out) {
    const unsigned FULL = 0xffffffffu;
    int wid  = blockIdx.x * 8 + (threadIdx.x >> 5);
    int lane = threadIdx.x & 31;

    int h = wid & 7;
    int bq = wid >> 3;          // b*NQ + q, 0..43519
    int b = bq / NQ;

    // one coalesced load each
    float myoff = off[(size_t)bq * 256 + h * 32 + lane];
    float logit = (lane < 16) ? logits[(size_t)bq * 128 + h * 16 + lane] : -1e30f;
    float myref = (lane < 8)  ? refp[(size_t)bq * 8 + lane] : 0.0f;

    // softmax over 16 lanes (xor offsets <= 8 stay within each 16-lane group)
    float m = logit;
#pragma unroll
    for (int o = 8; o > 0; o >>= 1) m = fmaxf(m, __shfl_xor_sync(FULL, m, o));
    float e = (lane < 16) ? __expf(logit - m) : 0.0f;
    float s = e;
#pragma unroll
    for (int o = 8; o > 0; o >>= 1) s += __shfl_xor_sync(FULL, s, o);
    float w16 = e / s;   // valid on lanes 0..15

    const float* vbase = val + (size_t)b * NV * 256 + h * 32 + lane;

    float acc = 0.0f;
#pragma unroll
    for (int p = 0; p < 16; p++) {
        const int l = p >> 2;
        float aw = __shfl_sync(FULL, w16, p);
        float ox = __shfl_sync(FULL, myoff, 2 * p);
        float oy = __shfl_sync(FULL, myoff, 2 * p + 1);
        float rx = __shfl_sync(FULL, myref, 2 * l);
        float ry = __shfl_sync(FULL, myref, 2 * l + 1);

        const int Wl = LVL_W[l], Hl = LVL_H[l], st = LVL_S[l];
        // x = ((2*loc-1)+1)*0.5*W - 0.5 = loc*W - 0.5, loc = ref + off/W
        float x = rx * (float)Wl + ox - 0.5f;
        float y = ry * (float)Hl + oy - 0.5f;
        float xf = floorf(x), yf = floorf(y);
        int x0 = (int)xf, y0 = (int)yf;
        float fx = x - xf, fy = y - yf;

        float w00 = (1.0f - fx) * (1.0f - fy) * aw;
        float w10 = fx * (1.0f - fy) * aw;
        float w01 = (1.0f - fx) * fy * aw;
        float w11 = fx * fy * aw;

        bool vx0 = (x0 >= 0) && (x0 <= Wl - 1);
        bool vx1 = (x0 + 1 >= 0) && (x0 + 1 <= Wl - 1);
        bool vy0 = (y0 >= 0) && (y0 <= Hl - 1);
        bool vy1 = (y0 + 1 >= 0) && (y0 + 1 <= Hl - 1);

        if (vx0 && vy0) acc = fmaf(w00, vbase[(size_t)(st + y0 * Wl + x0) * 256], acc);
        if (vx1 && vy0) acc = fmaf(w10, vbase[(size_t)(st + y0 * Wl + x0 + 1) * 256], acc);
        if (vx0 && vy1) acc = fmaf(w01, vbase[(size_t)(st + (y0 + 1) * Wl + x0) * 256], acc);
        if (vx1 && vy1) acc = fmaf(w11, vbase[(size_t)(st + (y0 + 1) * Wl + x0 + 1) * 256], acc);
    }

    out[(size_t)bq * 256 + h * 32 + lane] = acc;
}

// ---------------------------------------------------------------------------
// kernel_launch
// Inputs (metadata order): 0 query, 1 value, 2 reference_points, 3 spatial_shapes,
// 4 W_off, 5 b_off, 6 W_attn, 7 b_attn, 8 W_v, 9 b_v, 10 W_out, 11 b_out
// ---------------------------------------------------------------------------
extern "C" void kernel_launch(void* const* d_in, const int* in_sizes, int n_in,
                              void* d_out, int out_size) {
    const float* query = (const float*)d_in[0];
    const float* value = (const float*)d_in[1];
    const float* refp  = (const float*)d_in[2];
    const float* W_off = (const float*)d_in[4];
    const float* b_off = (const float*)d_in[5];
    const float* W_att = (const float*)d_in[6];
    const float* b_att = (const float*)d_in[7];
    const float* W_v   = (const float*)d_in[8];
    const float* b_v   = (const float*)d_in[9];
    const float* W_out = (const float*)d_in[10];
    const float* b_out = (const float*)d_in[11];
    float* out = (float*)d_out;

    float *p_val, *p_off, *p_attn, *p_samp;
    cudaGetSymbolAddress((void**)&p_val,  g_val);
    cudaGetSymbolAddress((void**)&p_off,  g_off);
    cudaGetSymbolAddress((void**)&p_attn, g_attn);
    cudaGetSymbolAddress((void**)&p_samp, g_samp);

    dim3 blk(256);
    dim3 g256(MROWS / BM, 256 / BN);   // (340, 2)
    dim3 g128(MROWS / BM, 128 / BN);   // (340, 1)

    // 1) val = value @ W_v + b_v
    gemm_k256<<<g256, blk>>>(value, W_v, b_v, p_val, 256);
    // 2) off = query @ W_off + b_off
    gemm_k256<<<g256, blk>>>(query, W_off, b_off, p_off, 256);
    // 3) attn logits = query @ W_attn + b_attn
    gemm_k256<<<g128, blk>>>(query, W_att, b_att, p_attn, 128);
    // 4) deformable sampling (softmax fused)
    sampler<<<MROWS, blk>>>(p_val, p_off, p_attn, refp, p_samp);
    // 5) out = samp @ W_out + b_out
    gemm_k256<<<g256, blk>>>(p_samp, W_out, b_out, out, 256);
}

// round 3
// speedup vs baseline: 2.1824x; 2.1824x over previous
#include <cuda_runtime.h>
#include <cuda_bf16.h>
#include <math.h>
#include <stdint.h>

// Problem constants (fixed by the reference)
#define BS 2
#define NQ 21760
#define NV 21760
#define MROWS (BS * NQ)   // 43520

__device__ __constant__ int LVL_W[4] = {128, 64, 32, 16};
__device__ __constant__ int LVL_S[4] = {0, 16384, 20480, 21504};

// Scratch (allocation-free rule: __device__ globals)
__device__ float g_val [MROWS * 256];
__device__ float g_off [MROWS * 256];
__device__ float g_attn[MROWS * 128];
__device__ float g_samp[MROWS * 256];

// ---------------------------------------------------------------------------
// Split-precision bf16 GEMM on the tensor pipe.
// C[M,N] = A[M,256] @ B[256,N] + bias[N], fp32 in/out.
// Each fp32 value v = hi(v) + lo(v), both bf16. Product uses hh + hl + lh
// (ll dropped, ~2^-18 relative) -> ~1e-5 overall error, far under 1e-3.
// Tile: 128x128, BK=16, 256 threads = 8 warps (2x4), warp tile 64x32,
// mma.sync.m16n8k16 (4 m-tiles x 4 n-tiles x 3 passes = 48 HMMA / warp / iter).
// ---------------------------------------------------------------------------
#define ASTRIDE 12    // words per A-row in smem (8 used + 4 pad) -> conflict-free frags
#define BSTRIDE 136   // words per B-k2row in smem (128 used + 8 pad)

__device__ __forceinline__ void split2(float x, float y, uint32_t &hi, uint32_t &lo) {
    __nv_bfloat16 hx = __float2bfloat16_rn(x);
    __nv_bfloat16 hy = __float2bfloat16_rn(y);
    __nv_bfloat16 lx = __float2bfloat16_rn(x - __bfloat162float(hx));
    __nv_bfloat16 ly = __float2bfloat16_rn(y - __bfloat162float(hy));
    hi = ((uint32_t)__bfloat16_as_ushort(hy) << 16) | (uint32_t)__bfloat16_as_ushort(hx);
    lo = ((uint32_t)__bfloat16_as_ushort(ly) << 16) | (uint32_t)__bfloat16_as_ushort(lx);
}

__device__ __forceinline__ void mma_bf16(float *d, const uint32_t *a, const uint32_t *b) {
    asm volatile(
        "mma.sync.aligned.m16n8k16.row.col.f32.bf16.bf16.f32 "
        "{%0,%1,%2,%3}, {%4,%5,%6,%7}, {%8,%9}, {%0,%1,%2,%3};\n"
        : "+f"(d[0]), "+f"(d[1]), "+f"(d[2]), "+f"(d[3])
        : "r"(a[0]), "r"(a[1]), "r"(a[2]), "r"(a[3]), "r"(b[0]), "r"(b[1]));
}

__global__ __launch_bounds__(256)
void gemm_bf16split(const float* __restrict__ A, const float* __restrict__ B,
                    const float* __restrict__ bias, float* __restrict__ C, int N)
{
    __shared__ uint32_t Ah[2][128 * ASTRIDE];
    __shared__ uint32_t Al[2][128 * ASTRIDE];
    __shared__ uint32_t Bh[2][8 * BSTRIDE];
    __shared__ uint32_t Bl[2][8 * BSTRIDE];

    const int tid  = threadIdx.x;
    const int lane = tid & 31;
    const int warp = tid >> 5;
    const int g = lane >> 2;       // groupID
    const int t = lane & 3;        // threadID in group
    const int warp_m = (warp >> 2) * 64;
    const int warp_n = (warp & 3) * 32;
    const int bm = blockIdx.x * 128;
    const int bn = blockIdx.y * 128;

    // staging thread mapping
    const int am  = tid >> 1;          // 0..127 (A row)
    const int ak  = (tid & 1) * 8;     // 0 or 8 (A k offset)
    const int bk2 = tid >> 5;          // 0..7 (B k-pair row)
    const int bn0 = (tid & 31) * 4;    // 0..124 (B col)

    float acc[4][4][4];
#pragma unroll
    for (int i = 0; i < 4; i++)
#pragma unroll
        for (int j = 0; j < 4; j++)
#pragma unroll
            for (int r = 0; r < 4; r++) acc[i][j][r] = 0.0f;

    float4 a0r, a1r, b0r, b1r;

    // ---- load tile 0
    {
        const float* Ap = &A[(size_t)(bm + am) * 256];
        a0r = *(const float4*)&Ap[ak];
        a1r = *(const float4*)&Ap[ak + 4];
        b0r = *(const float4*)&B[(size_t)(2 * bk2) * N + bn + bn0];
        b1r = *(const float4*)&B[(size_t)(2 * bk2 + 1) * N + bn + bn0];
    }
    // ---- convert + store tile 0 into buf 0
    {
        float fa[8] = {a0r.x, a0r.y, a0r.z, a0r.w, a1r.x, a1r.y, a1r.z, a1r.w};
        uint32_t h[4], l[4];
#pragma unroll
        for (int j = 0; j < 4; j++) split2(fa[2 * j], fa[2 * j + 1], h[j], l[j]);
        *(uint4*)&Ah[0][am * ASTRIDE + (ak >> 1)] = make_uint4(h[0], h[1], h[2], h[3]);
        *(uint4*)&Al[0][am * ASTRIDE + (ak >> 1)] = make_uint4(l[0], l[1], l[2], l[3]);
        float f0[4] = {b0r.x, b0r.y, b0r.z, b0r.w};
        float f1[4] = {b1r.x, b1r.y, b1r.z, b1r.w};
#pragma unroll
        for (int j = 0; j < 4; j++) split2(f0[j], f1[j], h[j], l[j]);
        *(uint4*)&Bh[0][bk2 * BSTRIDE + bn0] = make_uint4(h[0], h[1], h[2], h[3]);
        *(uint4*)&Bl[0][bk2 * BSTRIDE + bn0] = make_uint4(l[0], l[1], l[2], l[3]);
    }
    __syncthreads();

    for (int it = 0; it < 16; it++) {
        const int cur = it & 1;
        if (it < 15) {
            const int k0 = (it + 1) * 16;
            const float* Ap = &A[(size_t)(bm + am) * 256 + k0];
            a0r = *(const float4*)&Ap[ak];
            a1r = *(const float4*)&Ap[ak + 4];
            b0r = *(const float4*)&B[(size_t)(k0 + 2 * bk2) * N + bn + bn0];
            b1r = *(const float4*)&B[(size_t)(k0 + 2 * bk2 + 1) * N + bn + bn0];
        }

        // ---- compute on buf cur (one k16 step)
        {
            uint32_t afh[4][4], afl[4][4], bfh[4][2], bfl[4][2];
#pragma unroll
            for (int mt = 0; mt < 4; mt++) {
                int r0 = (warp_m + mt * 16 + g) * ASTRIDE;
                int r1 = r0 + 8 * ASTRIDE;
                afh[mt][0] = Ah[cur][r0 + t];
                afh[mt][1] = Ah[cur][r1 + t];
                afh[mt][2] = Ah[cur][r0 + t + 4];
                afh[mt][3] = Ah[cur][r1 + t + 4];
                afl[mt][0] = Al[cur][r0 + t];
                afl[mt][1] = Al[cur][r1 + t];
                afl[mt][2] = Al[cur][r0 + t + 4];
                afl[mt][3] = Al[cur][r1 + t + 4];
            }
#pragma unroll
            for (int nt = 0; nt < 4; nt++) {
                int cb = warp_n + nt * 8 + g;
                bfh[nt][0] = Bh[cur][t * BSTRIDE + cb];
                bfh[nt][1] = Bh[cur][(t + 4) * BSTRIDE + cb];
                bfl[nt][0] = Bl[cur][t * BSTRIDE + cb];
                bfl[nt][1] = Bl[cur][(t + 4) * BSTRIDE + cb];
            }
#pragma unroll
            for (int mt = 0; mt < 4; mt++)
#pragma unroll
                for (int nt = 0; nt < 4; nt++) {
                    mma_bf16(acc[mt][nt], afl[mt], bfh[nt]);
                    mma_bf16(acc[mt][nt], afh[mt], bfl[nt]);
                    mma_bf16(acc[mt][nt], afh[mt], bfh[nt]);
                }
        }

        if (it < 15) {
            const int nxt = cur ^ 1;
            float fa[8] = {a0r.x, a0r.y, a0r.z, a0r.w, a1r.x, a1r.y, a1r.z, a1r.w};
            uint32_t h[4], l[4];
#pragma unroll
            for (int j = 0; j < 4; j++) split2(fa[2 * j], fa[2 * j + 1], h[j], l[j]);
            *(uint4*)&Ah[nxt][am * ASTRIDE + (ak >> 1)] = make_uint4(h[0], h[1], h[2], h[3]);
            *(uint4*)&Al[nxt][am * ASTRIDE + (ak >> 1)] = make_uint4(l[0], l[1], l[2], l[3]);
            float f0[4] = {b0r.x, b0r.y, b0r.z, b0r.w};
            float f1[4] = {b1r.x, b1r.y, b1r.z, b1r.w};
#pragma unroll
            for (int j = 0; j < 4; j++) split2(f0[j], f1[j], h[j], l[j]);
            *(uint4*)&Bh[nxt][bk2 * BSTRIDE + bn0] = make_uint4(h[0], h[1], h[2], h[3]);
            *(uint4*)&Bl[nxt][bk2 * BSTRIDE + bn0] = make_uint4(l[0], l[1], l[2], l[3]);
            __syncthreads();
        }
    }

    // ---- epilogue: add bias, write fp32
#pragma unroll
    for (int mt = 0; mt < 4; mt++) {
        int row0 = bm + warp_m + mt * 16 + g;
#pragma unroll
        for (int nt = 0; nt < 4; nt++) {
            int col = bn + warp_n + nt * 8 + 2 * t;
            float2 bv = *(const float2*)&bias[col];
            float2 v0 = {acc[mt][nt][0] + bv.x, acc[mt][nt][1] + bv.y};
            float2 v1 = {acc[mt][nt][2] + bv.x, acc[mt][nt][3] + bv.y};
            *(float2*)&C[(size_t)row0 * N + col] = v0;
            *(float2*)&C[(size_t)(row0 + 8) * N + col] = v1;
        }
    }
}

// ---------------------------------------------------------------------------
// Deformable sampler v2: one warp per (b, q, h).
// Lanes 0..15 precompute point p's 4 clamped indices (pre-scaled by 256) and
// 4 masked weights IN PARALLEL, stash 32B in smem; main loop per point is
// 2x lds.128 (uniform broadcast) + 4 gathers + 4 FMA.
// ---------------------------------------------------------------------------
__global__ __launch_bounds__(256)
void sampler(const float* __restrict__ val, const float* __restrict__ off,
             const float* __restrict__ logits, const float* __restrict__ refp,
             float* __restrict__ out) {
    __shared__ __align__(16) float sm[8][16][8];   // [warp][point][i00,i10,i01,i11,w00,w10,w01,w11]
    const unsigned FULL = 0xffffffffu;
    const int warp = threadIdx.x >> 5;
    const int lane = threadIdx.x & 31;
    const int wid  = blockIdx.x * 8 + warp;

    const int h  = wid & 7;
    const int bq = wid >> 3;
    const int b  = (bq >= NQ) ? 1 : 0;

    // coalesced loads
    float myoff = off[(size_t)bq * 256 + h * 32 + lane];
    float logit = (lane < 16) ? logits[(size_t)bq * 128 + h * 16 + lane] : -1e30f;
    float myref = (lane < 8)  ? refp[(size_t)bq * 8 + lane] : 0.0f;

    // softmax over 16 logits (xor widths <= 8 stay inside each 16-lane half)
    float m = logit;
#pragma unroll
    for (int o = 8; o > 0; o >>= 1) m = fmaxf(m, __shfl_xor_sync(FULL, m, o));
    float e = (lane < 16) ? __expf(logit - m) : 0.0f;
    float s = e;
#pragma unroll
    for (int o = 8; o > 0; o >>= 1) s += __shfl_xor_sync(FULL, s, o);
    float aw = e / s;   // lane p (<16) holds point p's attention weight

    // per-point precompute on lanes 0..15 (16..31 duplicate harmlessly)
    {
        int p = lane & 15;
        int l = p >> 2;
        float ox = __shfl_sync(FULL, myoff, 2 * p);
        float oy = __shfl_sync(FULL, myoff, 2 * p + 1);
        float rx = __shfl_sync(FULL, myref, 2 * l);
        float ry = __shfl_sync(FULL, myref, 2 * l + 1);

        const int Wl = LVL_W[l];
        const int st = LVL_S[l];
        float x = rx * (float)Wl + ox - 0.5f;
        float y = ry * (float)Wl + oy - 0.5f;   // H == W for all levels
        float xf = floorf(x), yf = floorf(y);
        int x0 = (int)xf, y0 = (int)yf;
        float fx = x - xf, fy = y - yf;

        float w00 = (1.0f - fx) * (1.0f - fy) * aw;
        float w10 = fx * (1.0f - fy) * aw;
        float w01 = (1.0f - fx) * fy * aw;
        float w11 = fx * fy * aw;

        bool vx0 = (x0 >= 0) && (x0 < Wl);
        bool vx1 = (x0 + 1 >= 0) && (x0 + 1 < Wl);
        bool vy0 = (y0 >= 0) && (y0 < Wl);
        bool vy1 = (y0 + 1 >= 0) && (y0 + 1 < Wl);
        w00 = (vx0 && vy0) ? w00 : 0.0f;
        w10 = (vx1 && vy0) ? w10 : 0.0f;
        w01 = (vx0 && vy1) ? w01 : 0.0f;
        w11 = (vx1 && vy1) ? w11 : 0.0f;

        int xc0 = min(max(x0, 0), Wl - 1);
        int xc1 = min(max(x0 + 1, 0), Wl - 1);
        int yc0 = min(max(y0, 0), Wl - 1);
        int yc1 = min(max(y0 + 1, 0), Wl - 1);

        int i00 = (st + yc0 * Wl + xc0) << 8;   // element offsets pre-scaled by 256
        int i10 = (st + yc0 * Wl + xc1) << 8;
        int i01 = (st + yc1 * Wl + xc0) << 8;
        int i11 = (st + yc1 * Wl + xc1) << 8;

        if (lane < 16) {
            *(int4*)&sm[warp][p][0]   = make_int4(i00, i10, i01, i11);
            *(float4*)&sm[warp][p][4] = make_float4(w00, w10, w01, w11);
        }
    }
    __syncwarp();

    const float* vl = val + (size_t)b * (NV * 256) + h * 32 + lane;

    float acc = 0.0f;
#pragma unroll
    for (int p = 0; p < 16; p++) {
        int4   ii = *(const int4*)&sm[warp][p][0];
        float4 ww = *(const float4*)&sm[warp][p][4];
        acc = fmaf(ww.x, vl[ii.x], acc);
        acc = fmaf(ww.y, vl[ii.y], acc);
        acc = fmaf(ww.z, vl[ii.z], acc);
        acc = fmaf(ww.w, vl[ii.w], acc);
    }

    out[(size_t)bq * 256 + h * 32 + lane] = acc;
}

// ---------------------------------------------------------------------------
// kernel_launch
// Inputs: 0 query, 1 value, 2 reference_points, 3 spatial_shapes,
// 4 W_off, 5 b_off, 6 W_attn, 7 b_attn, 8 W_v, 9 b_v, 10 W_out, 11 b_out
// ---------------------------------------------------------------------------
extern "C" void kernel_launch(void* const* d_in, const int* in_sizes, int n_in,
                              void* d_out, int out_size) {
    const float* query = (const float*)d_in[0];
    const float* value = (const float*)d_in[1];
    const float* refp  = (const float*)d_in[2];
    const float* W_off = (const float*)d_in[4];
    const float* b_off = (const float*)d_in[5];
    const float* W_att = (const float*)d_in[6];
    const float* b_att = (const float*)d_in[7];
    const float* W_v   = (const float*)d_in[8];
    const float* b_v   = (const float*)d_in[9];
    const float* W_out = (const float*)d_in[10];
    const float* b_out = (const float*)d_in[11];
    float* out = (float*)d_out;

    float *p_val, *p_off, *p_attn, *p_samp;
    cudaGetSymbolAddress((void**)&p_val,  g_val);
    cudaGetSymbolAddress((void**)&p_off,  g_off);
    cudaGetSymbolAddress((void**)&p_attn, g_attn);
    cudaGetSymbolAddress((void**)&p_samp, g_samp);

    dim3 blk(256);
    dim3 g256(MROWS / 128, 2);
    dim3 g128(MROWS / 128, 1);

    gemm_bf16split<<<g256, blk>>>(value, W_v, b_v, p_val, 256);
    gemm_bf16split<<<g256, blk>>>(query, W_off, b_off, p_off, 256);
    gemm_bf16split<<<g128, blk>>>(query, W_att, b_att, p_attn, 128);
    sampler<<<MROWS, blk>>>(p_val, p_off, p_attn, refp, p_samp);
    gemm_bf16split<<<g256, blk>>>(p_samp, W_out, b_out, out, 256);
}